// round 11
// baseline (speedup 1.0000x reference)
#include <cuda_runtime.h>

#define NUM_RBF 64
#define CUTOFF  5.0f
#define MAX_G   64
#define BLOCK   960
#define NCTAS   148
#define WSTRIDE 68          // 64 + 4 pad floats -> bank-group = (row+quad) mod 8

// Packed node data: {x,y,z, bits(type | batch<<5)}. No other gmem scratch needed.
__device__ __align__(16) float4 g_pos4[65536];

__global__ void __launch_bounds__(256) prep_kernel(
        const float* __restrict__ pos,
        const int*   __restrict__ types,
        const int*   __restrict__ batch,
        float*       __restrict__ out,
        int N, int G) {
    int i = blockIdx.x * blockDim.x + threadIdx.x;
    if (i < G) out[i] = 0.0f;               // d_out is poisoned; zero it here
    if (i < N) {
        float4 p;
        p.x = pos[3 * i + 0];
        p.y = pos[3 * i + 1];
        p.z = pos[3 * i + 2];
        p.w = __int_as_float((types[i] & 31) | ((batch[i] & 63) << 5));
        g_pos4[i] = p;
    }
}

extern __shared__ float s_dyn[];

// DELTA = 5/63 split into fp32 hi + residual lo (folded at compile time);
// GAMMA = (64/5)^2; TWOGD = 2*gamma*DELTA; GD2 = gamma*DELTA^2;
// CMUL = exp(-2*gamma*DELTA^2).
#define F_DH      0.0793650793650794f
#define F_DL      ((float)(5.0 / 63.0 - (double)0.0793650793650794f))
#define F_INVD    12.6f
#define F_GAMMA   163.84f
#define F_GD2     1.0319979843990426f
#define F_TWOGD   26.006349206349206f
#define F_CMUL    0.1268725387859556f
#define F_PIOC    0.6283185307179586f

__device__ __forceinline__ void edge_compute(float4 a, float4 b, int T,
                                             const float* __restrict__ sw,
                                             float* __restrict__ esm) {
    float dx = b.x - a.x, dy = b.y - a.y, dz = b.z - a.z;
    float d = sqrtf(dx * dx + dy * dy + dz * dz + 1e-12f);
    if (d < CUTOFF) {
        int ab = __float_as_int(a.w);
        int bb = __float_as_int(b.w);
        int ta = ab & 31, tb = bb & 31;
        int g  = (ab >> 5) & 63;
        int lo = min(ta, tb), hi = max(ta, tb);
        const float* wp = sw + (lo * T + hi) * WSTRIDE;

        // Fixed 12-mu window of 3 aligned quads; mus within +-4*DELTA of d covered.
        int mc = (int)(d * F_INVD);                 // floor, d>=0
        int q0 = min(13, max(0, mc - 4) >> 2);
        wp += q0 * 4;

        // Two accurate direct seeds at window slots 5 and 6; split-DELTA offsets.
        // Chains run outward so near-d terms sit <= 2 steps from a seed.
        float i5 = (float)(q0 * 4 + 5);
        float i6 = i5 + 1.0f;
        float x5 = fmaf(i5, -F_DH, d); x5 = fmaf(i5, -F_DL, x5);
        float x6 = fmaf(i6, -F_DH, d); x6 = fmaf(i6, -F_DL, x6);
        float e5 = __expf(-F_GAMMA * x5 * x5);
        float e6 = __expf(-F_GAMMA * x6 * x6);
        float ru = __expf(fmaf( F_TWOGD, x6, -F_GD2));  // step k -> k+1 from slot 6
        float rd = __expf(fmaf(-F_TWOGD, x5, -F_GD2));  // step k -> k-1 from slot 5

        float4 w0 = *(const float4*)(wp);       // slots 0..3
        float4 w1 = *(const float4*)(wp + 4);   // slots 4..7
        float4 w2 = *(const float4*)(wp + 8);   // slots 8..11

        float acc = fmaf(w1.z, e6, w1.y * e5);                   // k=5,6
        float e = e6, r = ru;                                    // upward from 6
        e *= r; acc = fmaf(w1.w, e, acc); r *= F_CMUL;           // k=7
        e *= r; acc = fmaf(w2.x, e, acc); r *= F_CMUL;           // k=8
        e *= r; acc = fmaf(w2.y, e, acc); r *= F_CMUL;           // k=9
        e *= r; acc = fmaf(w2.z, e, acc); r *= F_CMUL;           // k=10
        e *= r; acc = fmaf(w2.w, e, acc);                        // k=11
        e = e5; r = rd;                                          // downward from 5
        e *= r; acc = fmaf(w1.x, e, acc); r *= F_CMUL;           // k=4
        e *= r; acc = fmaf(w0.w, e, acc); r *= F_CMUL;           // k=3
        e *= r; acc = fmaf(w0.z, e, acc); r *= F_CMUL;           // k=2
        e *= r; acc = fmaf(w0.y, e, acc); r *= F_CMUL;           // k=1
        e *= r; acc = fmaf(w0.x, e, acc);                        // k=0

        float fc = 0.5f * (__cosf(F_PIOC * d) + 1.0f);
        atomicAdd(&esm[g], acc * fc);
    }
}

__global__ void __launch_bounds__(BLOCK, 1) edge_kernel(
        const int*   __restrict__ ei,
        const float* __restrict__ rbf,
        const float* __restrict__ filt,
        float*       __restrict__ out,
        int E, int T) {
    const int rows = T * T;
    float* sw  = s_dyn;                   // rows * WSTRIDE floats, padded
    float* esm = s_dyn + rows * WSTRIDE;  // 64 graph bins
    int tid = threadIdx.x;

    // Build fused weight table (rbf * filt) directly in smem, padded stride.
    int nq = rows * (NUM_RBF / 4);
    for (int idx = tid; idx < nq; idx += BLOCK) {
        int r = idx >> 4, q = idx & 15;
        float4 va = __ldg((const float4*)rbf + idx);
        float4 vb = __ldg((const float4*)filt + idx);
        float4 w;
        w.x = va.x * vb.x; w.y = va.y * vb.y;
        w.z = va.z * vb.z; w.w = va.w * vb.w;
        *(float4*)&sw[r * WSTRIDE + q * 4] = w;
    }
    if (tid < MAX_G) esm[tid] = 0.0f;
    __syncthreads();

    if ((E & 3) == 0) {
        const int nquad  = E >> 2;
        const int stride = NCTAS * BLOCK;
        const int4* s4p = (const int4*)ei;
        const int4* d4p = (const int4*)(ei + E);
        int i = blockIdx.x * BLOCK + tid;
        if (i < nquad) {
            int4 s4 = __ldg(s4p + i);
            int4 d4 = __ldg(d4p + i);
            // Pipeline prologue: first half-batch gathers in flight.
            float4 xa0 = __ldg(&g_pos4[s4.x]);
            float4 xb0 = __ldg(&g_pos4[d4.x]);
            float4 xa1 = __ldg(&g_pos4[s4.y]);
            float4 xb1 = __ldg(&g_pos4[d4.y]);
            while (true) {
                // Second half-batch gathers; latency covered by compute(X) below.
                float4 ya0 = __ldg(&g_pos4[s4.z]);
                float4 yb0 = __ldg(&g_pos4[d4.z]);
                float4 ya1 = __ldg(&g_pos4[s4.w]);
                float4 yb1 = __ldg(&g_pos4[d4.w]);
                int inext = i + stride;
                bool more = inext < nquad;
                int4 s4n, d4n;
                if (more) { s4n = __ldg(s4p + inext); d4n = __ldg(d4p + inext); }

                edge_compute(xa0, xb0, T, sw, esm);
                edge_compute(xa1, xb1, T, sw, esm);

                if (more) {
                    // Next chunk's first half-batch; covered by compute(Y) below.
                    xa0 = __ldg(&g_pos4[s4n.x]);
                    xb0 = __ldg(&g_pos4[d4n.x]);
                    xa1 = __ldg(&g_pos4[s4n.y]);
                    xb1 = __ldg(&g_pos4[d4n.y]);
                }

                edge_compute(ya0, yb0, T, sw, esm);
                edge_compute(ya1, yb1, T, sw, esm);

                if (!more) break;
                s4 = s4n; d4 = d4n; i = inext;
            }
        }
    } else {
        for (int e = blockIdx.x * BLOCK + tid; e < E; e += NCTAS * BLOCK) {
            int src = __ldg(ei + e);
            int dst = __ldg(ei + e + E);
            float4 a = __ldg(&g_pos4[src]);
            float4 b = __ldg(&g_pos4[dst]);
            edge_compute(a, b, T, sw, esm);
        }
    }

    __syncthreads();
    if (tid < MAX_G) atomicAdd(&out[tid], esm[tid]);
}

extern "C" void kernel_launch(void* const* d_in, const int* in_sizes, int n_in,
                              void* d_out, int out_size) {
    const float* pos   = (const float*)d_in[0];
    const float* rbf   = (const float*)d_in[1];
    const float* filt  = (const float*)d_in[2];
    const int*   ei    = (const int*)d_in[3];
    const int*   types = (const int*)d_in[4];
    const int*   batch = (const int*)d_in[5];

    int N  = in_sizes[0] / 3;
    int WN = in_sizes[1];
    int E  = in_sizes[3] / 2;
    int G  = out_size < MAX_G ? out_size : MAX_G;

    int T = 1;
    while (T * T * NUM_RBF < WN) T++;      // 25 for this dataset

    int smem_bytes = T * T * WSTRIDE * 4 + MAX_G * 4;
    cudaFuncSetAttribute(edge_kernel,
                         cudaFuncAttributeMaxDynamicSharedMemorySize, smem_bytes);

    int prep_blocks = (N + 255) / 256;
    prep_kernel<<<prep_blocks, 256>>>(pos, types, batch, (float*)d_out, N, G);
    edge_kernel<<<NCTAS, BLOCK, smem_bytes>>>(ei, rbf, filt, (float*)d_out, E, T);
}

// round 16
// speedup vs baseline: 1.3464x; 1.3464x over previous
#include <cuda_runtime.h>

#define NUM_RBF 64
#define CUTOFF  5.0f
#define MAX_G   64
#define BLOCK   1024
#define NCTAS   148
#define WSTRIDE 68          // 64 + 4 pad floats -> bank-group = (row+quad) mod 8
#define PBLK    256

// Packed node data: {x,y,z, bits(type | batch<<5)}. No other gmem scratch needed.
__device__ __align__(16) float4 g_pos4[65536];

__global__ void __launch_bounds__(PBLK) prep_kernel(
        const float* __restrict__ pos,
        const int*   __restrict__ types,
        const int*   __restrict__ batch,
        float*       __restrict__ out,
        int N, int G) {
    __shared__ float spos[PBLK * 3];
    int tid  = threadIdx.x;
    int base = blockIdx.x * PBLK;          // first node of this CTA's slab
    int gi   = base + tid;

    if (blockIdx.x == 0 && tid < G) out[tid] = 0.0f;   // d_out poisoned; zero it

    // Coalesced slab load: 3 full-width passes over pos[base*3 .. base*3+767].
    int fbase = base * 3;
    int nf    = min(PBLK * 3, N * 3 - fbase);          // floats in this slab
    #pragma unroll
    for (int k = 0; k < 3; ++k) {
        int o = k * PBLK + tid;
        if (o < nf) spos[o] = pos[fbase + o];
    }
    __syncthreads();

    if (gi < N) {
        float4 p;
        p.x = spos[tid * 3 + 0];           // stride 3: conflict-free (gcd(3,32)=1)
        p.y = spos[tid * 3 + 1];
        p.z = spos[tid * 3 + 2];
        p.w = __int_as_float((types[gi] & 31) | ((batch[gi] & 63) << 5));
        g_pos4[gi] = p;
    }
}

extern __shared__ float s_dyn[];

// DELTA = 5/63 split into fp32 hi + residual lo (folded at compile time);
// GAMMA = (64/5)^2; TWOGD = 2*gamma*DELTA; GD2 = gamma*DELTA^2;
// CMUL = exp(-2*gamma*DELTA^2).
#define F_DH      0.0793650793650794f
#define F_DL      ((float)(5.0 / 63.0 - (double)0.0793650793650794f))
#define F_INVD    12.6f
#define F_GAMMA   163.84f
#define F_GD2     1.0319979843990426f
#define F_TWOGD   26.006349206349206f
#define F_CMUL    0.1268725387859556f
#define F_PIOC    0.6283185307179586f

__device__ __forceinline__ void edge_compute(float4 a, float4 b, int T,
                                             const float* __restrict__ sw,
                                             float* __restrict__ esm) {
    float dx = b.x - a.x, dy = b.y - a.y, dz = b.z - a.z;
    float d = sqrtf(dx * dx + dy * dy + dz * dz + 1e-12f);
    if (d < CUTOFF) {
        int ab = __float_as_int(a.w);
        int bb = __float_as_int(b.w);
        int ta = ab & 31, tb = bb & 31;
        int g  = (ab >> 5) & 63;
        int lo = min(ta, tb), hi = max(ta, tb);
        const float* wp = sw + (lo * T + hi) * WSTRIDE;

        // Fixed 12-mu window of 3 aligned quads; mus within +-4*DELTA of d covered.
        int mc = (int)(d * F_INVD);                 // floor, d>=0
        int q0 = min(13, max(0, mc - 4) >> 2);
        wp += q0 * 4;

        // Two accurate direct seeds at window slots 5 and 6; split-DELTA offsets.
        // Chains run outward so near-d terms sit <= 2 steps from a seed.
        float i5 = (float)(q0 * 4 + 5);
        float i6 = i5 + 1.0f;
        float x5 = fmaf(i5, -F_DH, d); x5 = fmaf(i5, -F_DL, x5);
        float x6 = fmaf(i6, -F_DH, d); x6 = fmaf(i6, -F_DL, x6);
        float e5 = __expf(-F_GAMMA * x5 * x5);
        float e6 = __expf(-F_GAMMA * x6 * x6);
        float ru = __expf(fmaf( F_TWOGD, x6, -F_GD2));  // step k -> k+1 from slot 6
        float rd = __expf(fmaf(-F_TWOGD, x5, -F_GD2));  // step k -> k-1 from slot 5

        float4 w0 = *(const float4*)(wp);       // slots 0..3
        float4 w1 = *(const float4*)(wp + 4);   // slots 4..7
        float4 w2 = *(const float4*)(wp + 8);   // slots 8..11

        float acc = fmaf(w1.z, e6, w1.y * e5);                   // k=5,6
        float e = e6, r = ru;                                    // upward from 6
        e *= r; acc = fmaf(w1.w, e, acc); r *= F_CMUL;           // k=7
        e *= r; acc = fmaf(w2.x, e, acc); r *= F_CMUL;           // k=8
        e *= r; acc = fmaf(w2.y, e, acc); r *= F_CMUL;           // k=9
        e *= r; acc = fmaf(w2.z, e, acc); r *= F_CMUL;           // k=10
        e *= r; acc = fmaf(w2.w, e, acc);                        // k=11
        e = e5; r = rd;                                          // downward from 5
        e *= r; acc = fmaf(w1.x, e, acc); r *= F_CMUL;           // k=4
        e *= r; acc = fmaf(w0.w, e, acc); r *= F_CMUL;           // k=3
        e *= r; acc = fmaf(w0.z, e, acc); r *= F_CMUL;           // k=2
        e *= r; acc = fmaf(w0.y, e, acc); r *= F_CMUL;           // k=1
        e *= r; acc = fmaf(w0.x, e, acc);                        // k=0

        float fc = 0.5f * (__cosf(F_PIOC * d) + 1.0f);
        atomicAdd(&esm[g], acc * fc);
    }
}

__global__ void __launch_bounds__(BLOCK, 1) edge_kernel(
        const int*   __restrict__ ei,
        const float* __restrict__ rbf,
        const float* __restrict__ filt,
        float*       __restrict__ out,
        int E, int T) {
    const int rows = T * T;
    float* sw  = s_dyn;                   // rows * WSTRIDE floats, padded
    float* esm = s_dyn + rows * WSTRIDE;  // 64 graph bins
    int tid = threadIdx.x;

    // Build fused weight table (rbf * filt) directly in smem, padded stride.
    int nq = rows * (NUM_RBF / 4);
    for (int idx = tid; idx < nq; idx += BLOCK) {
        int r = idx >> 4, q = idx & 15;
        float4 va = __ldg((const float4*)rbf + idx);
        float4 vb = __ldg((const float4*)filt + idx);
        float4 w;
        w.x = va.x * vb.x; w.y = va.y * vb.y;
        w.z = va.z * vb.z; w.w = va.w * vb.w;
        *(float4*)&sw[r * WSTRIDE + q * 4] = w;
    }
    if (tid < MAX_G) esm[tid] = 0.0f;
    __syncthreads();

    if ((E & 3) == 0) {
        const int nquad  = E >> 2;
        const int stride = NCTAS * BLOCK;
        const int4* s4p = (const int4*)ei;
        const int4* d4p = (const int4*)(ei + E);
        int i = blockIdx.x * BLOCK + tid;
        if (i < nquad) {
            int4 s4 = __ldg(s4p + i);
            int4 d4 = __ldg(d4p + i);
            while (true) {
                // Issue all 8 gathers up front for MLP; all die inside this
                // iteration (no cross-call live ranges -> no spills).
                float4 a0 = __ldg(&g_pos4[s4.x]);
                float4 b0 = __ldg(&g_pos4[d4.x]);
                float4 a1 = __ldg(&g_pos4[s4.y]);
                float4 b1 = __ldg(&g_pos4[d4.y]);
                float4 a2 = __ldg(&g_pos4[s4.z]);
                float4 b2 = __ldg(&g_pos4[d4.z]);
                float4 a3 = __ldg(&g_pos4[s4.w]);
                float4 b3 = __ldg(&g_pos4[d4.w]);
                // Prefetch next iteration's indices behind the gathers.
                int inext = i + stride;
                bool more = inext < nquad;
                int4 s4n, d4n;
                if (more) { s4n = __ldg(s4p + inext); d4n = __ldg(d4p + inext); }
                edge_compute(a0, b0, T, sw, esm);
                edge_compute(a1, b1, T, sw, esm);
                edge_compute(a2, b2, T, sw, esm);
                edge_compute(a3, b3, T, sw, esm);
                if (!more) break;
                s4 = s4n; d4 = d4n; i = inext;
            }
        }
    } else {
        for (int e = blockIdx.x * BLOCK + tid; e < E; e += NCTAS * BLOCK) {
            int src = __ldg(ei + e);
            int dst = __ldg(ei + e + E);
            float4 a = __ldg(&g_pos4[src]);
            float4 b = __ldg(&g_pos4[dst]);
            edge_compute(a, b, T, sw, esm);
        }
    }

    __syncthreads();
    if (tid < MAX_G) atomicAdd(&out[tid], esm[tid]);
}

extern "C" void kernel_launch(void* const* d_in, const int* in_sizes, int n_in,
                              void* d_out, int out_size) {
    const float* pos   = (const float*)d_in[0];
    const float* rbf   = (const float*)d_in[1];
    const float* filt  = (const float*)d_in[2];
    const int*   ei    = (const int*)d_in[3];
    const int*   types = (const int*)d_in[4];
    const int*   batch = (const int*)d_in[5];

    int N  = in_sizes[0] / 3;
    int WN = in_sizes[1];
    int E  = in_sizes[3] / 2;
    int G  = out_size < MAX_G ? out_size : MAX_G;

    int T = 1;
    while (T * T * NUM_RBF < WN) T++;      // 25 for this dataset

    int smem_bytes = T * T * WSTRIDE * 4 + MAX_G * 4;
    cudaFuncSetAttribute(edge_kernel,
                         cudaFuncAttributeMaxDynamicSharedMemorySize, smem_bytes);

    int prep_blocks = (N + PBLK - 1) / PBLK;
    prep_kernel<<<prep_blocks, PBLK>>>(pos, types, batch, (float*)d_out, N, G);
    edge_kernel<<<NCTAS, BLOCK, smem_bytes>>>(ei, rbf, filt, (float*)d_out, E, T);
}